// round 2
// baseline (speedup 1.0000x reference)
#include <cuda_runtime.h>
#include <math.h>

#define B_  4
#define L_  2048
#define D_  1024
#define H_  16
#define DH_ 64
#define BH_ (B_*H_)

// -------- scratch (device globals: allocation-free) --------
__device__ float g_q[(size_t)BH_*L_*DH_];
__device__ float g_k[(size_t)BH_*L_*DH_];
__device__ float g_v[(size_t)BH_*L_*DH_];

// ================= projection GEMM: Y = X @ W^T =================
// X [8192,1024] row-major, W [1024,1024] row-major [n][k] (torch Linear),
// Y scattered to [B,H,L,dh] head layout. Register double-buffered mainloop.
#define PBM 128
#define PBN 128
#define PBK 8
#define PST 132   // padded smem row stride (floats)

__global__ __launch_bounds__(256, 2)
void proj_kernel(const float* __restrict__ X, const float* __restrict__ W,
                 float* __restrict__ Y)
{
    __shared__ float sA[PBK][PST];
    __shared__ float sB[PBK][PST];

    const int tid = threadIdx.x;
    const int m0 = blockIdx.x * PBM;
    const int n0 = blockIdx.y * PBN;
    const int tx = tid & 15;        // 0..15 -> cols tx*8
    const int ty = tid >> 4;        // 0..15 -> rows ty*8

    const int lrow = tid >> 1;      // 0..127
    const int lk   = (tid & 1) * 4; // 0 or 4

    const float* xp = &X[(size_t)(m0 + lrow)*D_ + lk];
    const float* wp = &W[(size_t)(n0 + lrow)*D_ + lk];

    float acc[8][8];
    #pragma unroll
    for (int i = 0; i < 8; i++)
        #pragma unroll
        for (int j = 0; j < 8; j++) acc[i][j] = 0.f;

    // prologue: fetch k0=0 slice into registers
    float4 av = *(const float4*)&xp[0];
    float4 bv = *(const float4*)&wp[0];

    for (int k0 = 0; k0 < D_; k0 += PBK) {
        // deposit current slice into smem
        sA[lk+0][lrow] = av.x; sA[lk+1][lrow] = av.y;
        sA[lk+2][lrow] = av.z; sA[lk+3][lrow] = av.w;
        sB[lk+0][lrow] = bv.x; sB[lk+1][lrow] = bv.y;
        sB[lk+2][lrow] = bv.z; sB[lk+3][lrow] = bv.w;
        __syncthreads();

        // prefetch next slice (latency hidden behind the FMA loop below)
        if (k0 + PBK < D_) {
            av = *(const float4*)&xp[k0 + PBK];
            bv = *(const float4*)&wp[k0 + PBK];
        }

        #pragma unroll
        for (int kk = 0; kk < PBK; kk++) {
            float a[8], b[8];
            *(float4*)&a[0] = *(const float4*)&sA[kk][ty*8];
            *(float4*)&a[4] = *(const float4*)&sA[kk][ty*8+4];
            *(float4*)&b[0] = *(const float4*)&sB[kk][tx*8];
            *(float4*)&b[4] = *(const float4*)&sB[kk][tx*8+4];
            #pragma unroll
            for (int i = 0; i < 8; i++)
                #pragma unroll
                for (int j = 0; j < 8; j++)
                    acc[i][j] += a[i]*b[j];
        }
        __syncthreads();
    }

    // epilogue: scatter to [B,H,L,dh]
    const int nbase = n0 + tx*8;
    const int h  = nbase >> 6;
    const int d0 = nbase & 63;      // multiple of 8, stays within one head
    #pragma unroll
    for (int i = 0; i < 8; i++) {
        int m = m0 + ty*8 + i;
        int b = m >> 11;
        int l = m & (L_-1);
        float* yp = &Y[(((size_t)(b*H_ + h))*L_ + l)*DH_ + d0];
        float4 w1, w2;
        w1.x = acc[i][0]; w1.y = acc[i][1]; w1.z = acc[i][2]; w1.w = acc[i][3];
        w2.x = acc[i][4]; w2.y = acc[i][5]; w2.z = acc[i][6]; w2.w = acc[i][7];
        *(float4*)&yp[0] = w1;
        *(float4*)&yp[4] = w2;
    }
}

// ================= fused attention =================
// One CTA = (head bh, block of QB=16 query rows). Full 16x2048 score tile in
// smem -> exact softmax -> write attn once -> O = P@V streaming V chunks.
#define QB  16
#define KT  256               // K/V rows staged per chunk
#define KST 260               // padded stride for transposed K tile
#define SST 2052              // padded stride for score rows
#define SM_Q_OFF  (QB*SST)                 // 32832
#define SM_KV_OFF (SM_Q_OFF + DH_*20)      // +1280 = 34112
#define SM_FLOATS (SM_KV_OFF + DH_*KST)    // +16640 = 50752
#define SM_BYTES  (SM_FLOATS*4)            // 203008 < 227KB

__global__ __launch_bounds__(256, 1)
void attn_kernel(float* __restrict__ out, float* __restrict__ attn, int write_attn)
{
    extern __shared__ float sm[];
    float* sS  = sm;                // [16][2052]
    float* sQt = sm + SM_Q_OFF;     // [64][20]  Q transposed
    float* sKV = sm + SM_KV_OFF;    // [64][260] Kt  (reused as V [256][64])

    const int tid = threadIdx.x;
    const int bh  = blockIdx.y;               // 0..63
    const int qb0 = blockIdx.x * QB;
    const float* Qh = g_q + (size_t)bh * (L_*DH_);
    const float* Kh = g_k + (size_t)bh * (L_*DH_);
    const float* Vh = g_v + (size_t)bh * (L_*DH_);

    // ---- load Q block transposed: sQt[d][r] ----
    {
        int r = tid >> 4;             // 0..15
        int d = (tid & 15) << 2;      // 0..60
        float4 v = *(const float4*)&Qh[(size_t)(qb0 + r)*DH_ + d];
        sQt[(d+0)*20 + r] = v.x;
        sQt[(d+1)*20 + r] = v.y;
        sQt[(d+2)*20 + r] = v.z;
        sQt[(d+3)*20 + r] = v.w;
    }
    __syncthreads();

    const int ty = tid >> 6;          // 0..3  -> rows ty*4
    const int tx = tid & 63;          // cols tx*4 within chunk

    // ---- phase B: S = Q K^T / 8, chunk by chunk ----
    for (int kc = 0; kc < L_/KT; kc++) {
        const float* src = Kh + (size_t)kc * (KT*DH_);
        #pragma unroll 8
        for (int it = 0; it < (KT*DH_)/256; it++) {   // 64 coalesced scalar loads
            int idx = tid + it*256;
            int d = idx & 63;
            int l = idx >> 6;
            sKV[d*KST + l] = src[idx];                // transposed store
        }
        __syncthreads();

        float acc[4][4];
        #pragma unroll
        for (int i = 0; i < 4; i++)
            #pragma unroll
            for (int j = 0; j < 4; j++) acc[i][j] = 0.f;

        #pragma unroll 8
        for (int kk = 0; kk < DH_; kk++) {
            float a[4], bb[4];
            *(float4*)a  = *(const float4*)&sQt[kk*20  + (ty<<2)];
            *(float4*)bb = *(const float4*)&sKV[kk*KST + (tx<<2)];
            #pragma unroll
            for (int i = 0; i < 4; i++)
                #pragma unroll
                for (int j = 0; j < 4; j++)
                    acc[i][j] += a[i]*bb[j];
        }

        int col0 = kc*KT + (tx<<2);
        #pragma unroll
        for (int i = 0; i < 4; i++) {
            float4 w;
            w.x = acc[i][0]*0.125f; w.y = acc[i][1]*0.125f;
            w.z = acc[i][2]*0.125f; w.w = acc[i][3]*0.125f;
            *(float4*)&sS[((ty<<2)+i)*SST + col0] = w;
        }
        __syncthreads();
    }

    // ---- phase C: exact softmax per row (16 lanes per row) ----
    {
        int row  = tid >> 4;
        int lane = tid & 15;
        float* srow = sS + row*SST;
        float m = -3.4e38f;
        #pragma unroll 8
        for (int j = 0; j < L_/16; j++)
            m = fmaxf(m, srow[lane + (j<<4)]);
        #pragma unroll
        for (int o = 8; o >= 1; o >>= 1)
            m = fmaxf(m, __shfl_xor_sync(0xffffffffu, m, o));
        float s = 0.f;
        #pragma unroll 8
        for (int j = 0; j < L_/16; j++) {
            float e = __expf(srow[lane + (j<<4)] - m);
            srow[lane + (j<<4)] = e;
            s += e;
        }
        #pragma unroll
        for (int o = 8; o >= 1; o >>= 1)
            s += __shfl_xor_sync(0xffffffffu, s, o);
        float inv = 1.f / s;
        if (write_attn) {
            float* arow = attn + ((size_t)bh * L_ + (qb0 + row)) * L_;
            #pragma unroll 8
            for (int j = 0; j < L_/16; j++) {
                float p = srow[lane + (j<<4)] * inv;
                srow[lane + (j<<4)] = p;
                arow[lane + (j<<4)] = p;
            }
        } else {
            #pragma unroll 8
            for (int j = 0; j < L_/16; j++)
                srow[lane + (j<<4)] *= inv;
        }
    }

    // ---- phase D: O = P @ V ----
    float accO[4] = {0.f, 0.f, 0.f, 0.f};
    const int row2 = tid >> 4;          // 0..15
    const int dx   = (tid & 15) << 2;   // 0..60
    for (int kc = 0; kc < L_/KT; kc++) {
        __syncthreads();                // covers softmax (1st iter) & prior V reads
        {
            const float4* src = (const float4*)(Vh + (size_t)kc*(KT*DH_));
            float4* dst = (float4*)sKV;
            #pragma unroll
            for (int it = 0; it < (KT*DH_)/4/256; it++)  // 16 float4 copies
                dst[tid + it*256] = src[tid + it*256];
        }
        __syncthreads();
        const float* prow = sS + row2*SST + kc*KT;
        #pragma unroll 4
        for (int l = 0; l < KT; l += 4) {
            float4 p  = *(const float4*)&prow[l];
            float4 v0 = *(const float4*)&sKV[(l+0)*DH_ + dx];
            accO[0] += p.x*v0.x; accO[1] += p.x*v0.y; accO[2] += p.x*v0.z; accO[3] += p.x*v0.w;
            float4 v1 = *(const float4*)&sKV[(l+1)*DH_ + dx];
            accO[0] += p.y*v1.x; accO[1] += p.y*v1.y; accO[2] += p.y*v1.z; accO[3] += p.y*v1.w;
            float4 v2 = *(const float4*)&sKV[(l+2)*DH_ + dx];
            accO[0] += p.z*v2.x; accO[1] += p.z*v2.y; accO[2] += p.z*v2.z; accO[3] += p.z*v2.w;
            float4 v3 = *(const float4*)&sKV[(l+3)*DH_ + dx];
            accO[0] += p.w*v3.x; accO[1] += p.w*v3.y; accO[2] += p.w*v3.z; accO[3] += p.w*v3.w;
        }
    }
    {
        int b = bh >> 4, h = bh & 15;
        float4 w; w.x = accO[0]; w.y = accO[1]; w.z = accO[2]; w.w = accO[3];
        *(float4*)&out[((size_t)b*L_ + qb0 + row2)*D_ + h*DH_ + dx] = w;
    }
}

// ================= launch =================
extern "C" void kernel_launch(void* const* d_in, const int* in_sizes, int n_in,
                              void* d_out, int out_size)
{
    const float* query = (const float*)d_in[0];
    const float* key_  = (const float*)d_in[1];
    const float* value = (const float*)d_in[2];
    const float* w_q   = (const float*)d_in[3];
    const float* w_k   = (const float*)d_in[4];
    const float* w_v   = (const float*)d_in[5];
    float* out = (float*)d_out;

    float *qp, *kp, *vp;
    cudaGetSymbolAddress((void**)&qp, g_q);
    cudaGetSymbolAddress((void**)&kp, g_k);
    cudaGetSymbolAddress((void**)&vp, g_v);

    dim3 pg(8192/PBM, D_/PBN);   // (64, 8)
    proj_kernel<<<pg, 256>>>(query, w_q, qp);
    proj_kernel<<<pg, 256>>>(key_,  w_k, kp);
    proj_kernel<<<pg, 256>>>(value, w_v, vp);

    cudaFuncSetAttribute(attn_kernel,
                         cudaFuncAttributeMaxDynamicSharedMemorySize, SM_BYTES);

    long long need = (long long)B_*L_*D_ + (long long)BH_*L_*L_;
    int write_attn = ((long long)out_size >= need) ? 1 : 0;
    float* attn = out + (size_t)B_*L_*D_;

    dim3 ag(L_/QB, BH_);         // (128, 64)
    attn_kernel<<<ag, 256, SM_BYTES>>>(out, attn, write_attn);
}

// round 9
// speedup vs baseline: 3.4743x; 3.4743x over previous
#include <cuda_runtime.h>
#include <cuda_bf16.h>
#include <math.h>
#include <stdint.h>

#define B_  4
#define L_  2048
#define D_  1024
#define H_  16
#define DH_ 64
#define BH_ (B_*H_)

// bf16 hi/lo planes, [bh][l][dh]
__device__ __nv_bfloat16 g_qhi[(size_t)BH_*L_*DH_];
__device__ __nv_bfloat16 g_qlo[(size_t)BH_*L_*DH_];
__device__ __nv_bfloat16 g_khi[(size_t)BH_*L_*DH_];
__device__ __nv_bfloat16 g_klo[(size_t)BH_*L_*DH_];
__device__ __nv_bfloat16 g_vhi[(size_t)BH_*L_*DH_];
__device__ __nv_bfloat16 g_vlo[(size_t)BH_*L_*DH_];

__device__ __forceinline__ void mma_bf(float (&c)[4], uint32_t a0, uint32_t a1,
                                       uint32_t a2, uint32_t a3,
                                       uint32_t b0, uint32_t b1)
{
    asm volatile(
        "mma.sync.aligned.m16n8k16.row.col.f32.bf16.bf16.f32 "
        "{%0,%1,%2,%3},{%4,%5,%6,%7},{%8,%9},{%0,%1,%2,%3};\n"
        : "+f"(c[0]), "+f"(c[1]), "+f"(c[2]), "+f"(c[3])
        : "r"(a0), "r"(a1), "r"(a2), "r"(a3), "r"(b0), "r"(b1));
}

__device__ __forceinline__ void split_pack(float x, float y, uint32_t& h, uint32_t& l)
{
    __nv_bfloat16 hx = __float2bfloat16_rn(x);
    __nv_bfloat16 hy = __float2bfloat16_rn(y);
    __nv_bfloat16 lx = __float2bfloat16_rn(x - __bfloat162float(hx));
    __nv_bfloat16 ly = __float2bfloat16_rn(y - __bfloat162float(hy));
    __nv_bfloat162 hh; hh.x = hx; hh.y = hy;
    __nv_bfloat162 ll; ll.x = lx; ll.y = ly;
    h = *reinterpret_cast<uint32_t*>(&hh);
    l = *reinterpret_cast<uint32_t*>(&ll);
}

// ================= projection: Y = X @ W^T (bf16x3 MMA) =================
#define PJW 20   // smem row stride in words (40 halves = 32 data + 8 pad)

__global__ __launch_bounds__(256, 2)
void proj3_kernel(const float* __restrict__ X, const float* __restrict__ W,
                  __nv_bfloat16* __restrict__ Yh, __nv_bfloat16* __restrict__ Yl)
{
    __shared__ uint32_t sb[4*128*PJW];
    const int AHI = 0, ALO = 2560, BHI = 5120, BLO = 7680;

    const int tid = threadIdx.x;
    const int w = tid>>5, lane = tid&31, l4 = lane>>2, lr = lane&3;
    const int wM = w>>1, wN = w&1;
    const int m0 = blockIdx.x*128, n0 = blockIdx.y*128;
    const int row = tid>>1, kq = (tid&1)*16;

    const float* xp = X + (size_t)(m0+row)*D_ + kq;
    const float* wp = W + (size_t)(n0+row)*D_ + kq;

    float acc[2][8][4];
    #pragma unroll
    for (int mt=0;mt<2;mt++)
        #pragma unroll
        for (int nt=0;nt<8;nt++)
            #pragma unroll
            for (int i=0;i<4;i++) acc[mt][nt][i] = 0.f;

    float4 ax[4], bx[4];
    #pragma unroll
    for (int i=0;i<4;i++){ ax[i] = *(const float4*)&xp[4*i]; bx[i] = *(const float4*)&wp[4*i]; }

    for (int k0 = 0; k0 < D_; k0 += 32) {
        const int dw = row*PJW + (kq>>1);
        #pragma unroll
        for (int i=0;i<4;i++){
            uint32_t h0,l0,h1,l1;
            split_pack(ax[i].x, ax[i].y, h0, l0);
            split_pack(ax[i].z, ax[i].w, h1, l1);
            sb[AHI+dw+2*i] = h0; sb[AHI+dw+2*i+1] = h1;
            sb[ALO+dw+2*i] = l0; sb[ALO+dw+2*i+1] = l1;
            split_pack(bx[i].x, bx[i].y, h0, l0);
            split_pack(bx[i].z, bx[i].w, h1, l1);
            sb[BHI+dw+2*i] = h0; sb[BHI+dw+2*i+1] = h1;
            sb[BLO+dw+2*i] = l0; sb[BLO+dw+2*i+1] = l1;
        }
        __syncthreads();
        if (k0 + 32 < D_) {
            #pragma unroll
            for (int i=0;i<4;i++){
                ax[i] = *(const float4*)&xp[k0+32+4*i];
                bx[i] = *(const float4*)&wp[k0+32+4*i];
            }
        }
        #pragma unroll
        for (int kt=0;kt<2;kt++){
            uint32_t ah[2][4], al[2][4];
            #pragma unroll
            for (int mt=0;mt<2;mt++){
                int aw = (wM*32 + mt*16 + l4)*PJW + kt*8 + lr;
                ah[mt][0]=sb[AHI+aw];       ah[mt][1]=sb[AHI+aw+8*PJW];
                ah[mt][2]=sb[AHI+aw+4];     ah[mt][3]=sb[AHI+aw+8*PJW+4];
                al[mt][0]=sb[ALO+aw];       al[mt][1]=sb[ALO+aw+8*PJW];
                al[mt][2]=sb[ALO+aw+4];     al[mt][3]=sb[ALO+aw+8*PJW+4];
            }
            #pragma unroll
            for (int nt=0;nt<8;nt++){
                int bw = (wN*64 + nt*8 + l4)*PJW + kt*8 + lr;
                uint32_t bh0=sb[BHI+bw], bh1=sb[BHI+bw+4];
                uint32_t bl0=sb[BLO+bw], bl1=sb[BLO+bw+4];
                #pragma unroll
                for (int mt=0;mt<2;mt++){
                    mma_bf(acc[mt][nt], ah[mt][0],ah[mt][1],ah[mt][2],ah[mt][3], bh0,bh1);
                    mma_bf(acc[mt][nt], al[mt][0],al[mt][1],al[mt][2],al[mt][3], bh0,bh1);
                    mma_bf(acc[mt][nt], ah[mt][0],ah[mt][1],ah[mt][2],ah[mt][3], bl0,bl1);
                }
            }
        }
        __syncthreads();
    }

    // epilogue -> hi/lo planes [bh][l][dh]
    #pragma unroll
    for (int mt=0;mt<2;mt++){
        #pragma unroll
        for (int nt=0;nt<8;nt++){
            int m = m0 + wM*32 + mt*16 + l4;
            int n = n0 + wN*64 + nt*8 + 2*lr;
            int b = m>>11, l = m&2047, h = n>>6, dh = n&63;
            size_t o = (((size_t)(b*H_+h)*L_) + l)*DH_ + dh;
            uint32_t hi, lo;
            split_pack(acc[mt][nt][0], acc[mt][nt][1], hi, lo);
            *(uint32_t*)(Yh+o) = hi; *(uint32_t*)(Yl+o) = lo;
            split_pack(acc[mt][nt][2], acc[mt][nt][3], hi, lo);
            *(uint32_t*)(Yh+o+8*DH_) = hi; *(uint32_t*)(Yl+o+8*DH_) = lo;
        }
    }
}

// ================= attention (bf16x3 MMA, 2-sweep exact softmax) =================
#define AQ  64
#define ACH 128
#define NCH (L_/ACH)
#define QW  36     // q/k row stride words (72 halves)
#define VW  68     // vt row stride words (136 halves)
// word bases
#define QHW 0
#define QLW 2304
#define KHW 4608
#define KLW 9216
#define VHW 13824
#define VLW 18176
#define FLT_OFF 90112
#define ASMEM 109312
#define SCL 0.125f

__device__ __forceinline__ void compute_S(const uint32_t* sw, int qbase, int kb,
                                          float (&acc)[8][4])
{
    #pragma unroll
    for (int n=0;n<8;n++){ acc[n][0]=0.f; acc[n][1]=0.f; acc[n][2]=0.f; acc[n][3]=0.f; }
    #pragma unroll
    for (int kt=0;kt<4;kt++){
        int aw = qbase + kt*8;
        uint32_t ah0=sw[QHW+aw], ah1=sw[QHW+aw+8*QW], ah2=sw[QHW+aw+4], ah3=sw[QHW+aw+8*QW+4];
        uint32_t al0=sw[QLW+aw], al1=sw[QLW+aw+8*QW], al2=sw[QLW+aw+4], al3=sw[QLW+aw+8*QW+4];
        #pragma unroll
        for (int n=0;n<8;n++){
            int bw = kb + n*8*QW + kt*8;
            uint32_t bh0=sw[KHW+bw], bh1=sw[KHW+bw+4];
            uint32_t bl0=sw[KLW+bw], bl1=sw[KLW+bw+4];
            mma_bf(acc[n], ah0,ah1,ah2,ah3, bh0,bh1);
            mma_bf(acc[n], al0,al1,al2,al3, bh0,bh1);
            mma_bf(acc[n], ah0,ah1,ah2,ah3, bl0,bl1);
        }
    }
}

__global__ __launch_bounds__(256, 2)
void attn_mma_kernel(float* __restrict__ out, float* __restrict__ attn, int write_attn)
{
    extern __shared__ char smem_raw[];
    uint32_t* sw = (uint32_t*)smem_raw;
    __nv_bfloat16* sh = (__nv_bfloat16*)smem_raw;
    float* sPart = (float*)(smem_raw + FLT_OFF);
    float* sInv  = sPart + 128;
    float* sO    = sInv + 64;

    const int tid = threadIdx.x;
    const int w = tid>>5, lane = tid&31, l4 = lane>>2, lr = lane&3;
    const int mstrip = w>>1, khalf = w&1;
    const int bh = blockIdx.y;
    const int qb0 = blockIdx.x*AQ;

    // stage Q (contiguous 512 uint4 per plane)
    {
        const uint4* s1 = (const uint4*)(g_qhi + ((size_t)bh*L_ + qb0)*DH_);
        const uint4* s2 = (const uint4*)(g_qlo + ((size_t)bh*L_ + qb0)*DH_);
        #pragma unroll
        for (int i=0;i<2;i++){
            int j = tid + i*256;
            int dw = (j>>3)*QW + (j&7)*4;
            *(uint4*)&sw[QHW+dw] = s1[j];
            *(uint4*)&sw[QLW+dw] = s2[j];
        }
    }
    __syncthreads();

    const int qbase = (mstrip*16 + l4)*QW + lr;
    const int kb    = (khalf*64 + l4)*QW + lr;

    const __nv_bfloat16* Kh = g_khi + (size_t)bh*L_*DH_;
    const __nv_bfloat16* Kl = g_klo + (size_t)bh*L_*DH_;
    const __nv_bfloat16* Vh = g_vhi + (size_t)bh*L_*DH_;
    const __nv_bfloat16* Vl = g_vlo + (size_t)bh*L_*DH_;

    float rs0 = 0.f, rs1 = 0.f;

    // ---- sweep 1: row sums of exp ----
    for (int kc=0;kc<NCH;kc++){
        const uint4* skh = (const uint4*)(Kh + (size_t)kc*ACH*DH_);
        const uint4* skl = (const uint4*)(Kl + (size_t)kc*ACH*DH_);
        uint4 t0=skh[tid], t1=skh[tid+256], t2=skh[tid+512], t3=skh[tid+768];
        uint4 u0=skl[tid], u1=skl[tid+256], u2=skl[tid+512], u3=skl[tid+768];
        __syncthreads();
        {
            int j0=tid, j1=tid+256, j2=tid+512, j3=tid+768;
            *(uint4*)&sw[KHW+(j0>>3)*QW+(j0&7)*4] = t0;
            *(uint4*)&sw[KHW+(j1>>3)*QW+(j1&7)*4] = t1;
            *(uint4*)&sw[KHW+(j2>>3)*QW+(j2&7)*4] = t2;
            *(uint4*)&sw[KHW+(j3>>3)*QW+(j3&7)*4] = t3;
            *(uint4*)&sw[KLW+(j0>>3)*QW+(j0&7)*4] = u0;
            *(uint4*)&sw[KLW+(j1>>3)*QW+(j1&7)*4] = u1;
            *(uint4*)&sw[KLW+(j2>>3)*QW+(j2&7)*4] = u2;
            *(uint4*)&sw[KLW+(j3>>3)*QW+(j3&7)*4] = u3;
        }
        __syncthreads();
        float acc[8][4];
        compute_S(sw, qbase, kb, acc);
        #pragma unroll
        for (int n=0;n<8;n++){
            rs0 += __expf(acc[n][0]*SCL) + __expf(acc[n][1]*SCL);
            rs1 += __expf(acc[n][2]*SCL) + __expf(acc[n][3]*SCL);
        }
    }
    rs0 += __shfl_xor_sync(0xffffffffu, rs0, 1);
    rs0 += __shfl_xor_sync(0xffffffffu, rs0, 2);
    rs1 += __shfl_xor_sync(0xffffffffu, rs1, 1);
    rs1 += __shfl_xor_sync(0xffffffffu, rs1, 2);
    if (lr == 0){
        sPart[khalf*64 + mstrip*16 + l4]     = rs0;
        sPart[khalf*64 + mstrip*16 + l4 + 8] = rs1;
    }
    __syncthreads();
    if (tid < 64) sInv[tid] = 1.f / (sPart[tid] + sPart[64+tid]);
    __syncthreads();

    const float inv0 = sInv[mstrip*16 + l4];
    const float inv1 = sInv[mstrip*16 + l4 + 8];

    // ---- sweep 2: attn write + O = P@V ----
    float oacc[8][4];
    #pragma unroll
    for (int n=0;n<8;n++){ oacc[n][0]=0.f; oacc[n][1]=0.f; oacc[n][2]=0.f; oacc[n][3]=0.f; }

    float* attnRow = attn + ((size_t)bh*L_ + qb0 + mstrip*16 + l4)*L_;
    const int colb = khalf*64 + 2*lr;

    for (int kc=0;kc<NCH;kc++){
        const uint4* skh = (const uint4*)(Kh + (size_t)kc*ACH*DH_);
        const uint4* skl = (const uint4*)(Kl + (size_t)kc*ACH*DH_);
        const uint4* svh = (const uint4*)(Vh + (size_t)kc*ACH*DH_);
        const uint4* svl = (const uint4*)(Vl + (size_t)kc*ACH*DH_);
        uint4 t0=skh[tid], t1=skh[tid+256], t2=skh[tid+512], t3=skh[tid+768];
        uint4 u0=skl[tid], u1=skl[tid+256], u2=skl[tid+512], u3=skl[tid+768];
        __syncthreads();
        {
            int j0=tid, j1=tid+256, j2=tid+512, j3=tid+768;
            *(uint4*)&sw[KHW+(j0>>3)*QW+(j0&7)*4] = t0;
            *(uint4*)&sw[KHW+(j1>>3)*QW+(j1&7)*4] = t1;
            *(uint4*)&sw[KHW+(j2>>3)*QW+(j2&7)*4] = t2;
            *(uint4*)&sw[KHW+(j3>>3)*QW+(j3&7)*4] = t3;
            *(uint4*)&sw[KLW+(j0>>3)*QW+(j0&7)*4] = u0;
            *(uint4*)&sw[KLW+(j1>>3)*QW+(j1&7)*4] = u1;
            *(uint4*)&sw[KLW+(j2>>3)*QW+(j2&7)*4] = u2;
            *(uint4*)&sw[KLW+(j3>>3)*QW+(j3&7)*4] = u3;
        }
        // Vt staging (transpose in smem), XOR-swizzled half-column:
        // physical half col = l ^ ((dh>>3)<<1); here dh>>3 == (j&7) for all 8 q's.
        #pragma unroll
        for (int i=0;i<4;i++){
            int j = tid + i*256;
            uint4 v = svh[j];
            uint4 x = svl[j];
            int r = j>>3, sg = (j&7)*8;
            int rs = r ^ ((j&7)<<1);
            const __nv_bfloat16* pv = (const __nv_bfloat16*)&v;
            const __nv_bfloat16* px = (const __nv_bfloat16*)&x;
            #pragma unroll
            for (int q=0;q<8;q++){
                sh[2*VHW + (sg+q)*136 + rs] = pv[q];
                sh[2*VLW + (sg+q)*136 + rs] = px[q];
            }
        }
        __syncthreads();

        float acc[8][4];
        compute_S(sw, qbase, kb, acc);

        const int cb = kc*ACH + colb;
        #pragma unroll
        for (int j=0;j<4;j++){
            float e00=__expf(acc[2*j][0]*SCL)*inv0,  e01=__expf(acc[2*j][1]*SCL)*inv0;
            float e02=__expf(acc[2*j][2]*SCL)*inv1,  e03=__expf(acc[2*j][3]*SCL)*inv1;
            float f00=__expf(acc[2*j+1][0]*SCL)*inv0, f01=__expf(acc[2*j+1][1]*SCL)*inv0;
            float f02=__expf(acc[2*j+1][2]*SCL)*inv1, f03=__expf(acc[2*j+1][3]*SCL)*inv1;
            if (write_attn){
                float2 p;
                p.x=e00; p.y=e01; *(float2*)&attnRow[cb + j*16]          = p;
                p.x=e02; p.y=e03; *(float2*)&attnRow[8*L_ + cb + j*16]   = p;
                p.x=f00; p.y=f01; *(float2*)&attnRow[cb + j*16 + 8]      = p;
                p.x=f02; p.y=f03; *(float2*)&attnRow[8*L_ + cb + j*16+8] = p;
            }
            uint32_t a0h,a0l,a1h,a1l,a2h,a2l,a3h,a3l;
            split_pack(e00,e01,a0h,a0l);
            split_pack(e02,e03,a1h,a1l);
            split_pack(f00,f01,a2h,a2l);
            split_pack(f02,f03,a3h,a3l);
            const int cw = lr + khalf*32 + j*8;   // pre-swizzle word col
            #pragma unroll
            for (int n=0;n<8;n++){
                int rowb = (n*8 + l4)*VW;
                int b0 = rowb + (cw ^ n);
                int b1 = rowb + ((cw + 4) ^ n);
                uint32_t vh0=sw[VHW+b0], vh1=sw[VHW+b1];
                uint32_t vl0=sw[VLW+b0], vl1=sw[VLW+b1];
                mma_bf(oacc[n], a0h,a1h,a2h,a3h, vh0,vh1);
                mma_bf(oacc[n], a0l,a1l,a2l,a3l, vh0,vh1);
                mma_bf(oacc[n], a0h,a1h,a2h,a3h, vl0,vl1);
            }
        }
    }

    // O cross-warp (khalf) reduction + writeback
    __syncthreads();
    const int orow = mstrip*16 + l4;
    if (khalf == 1){
        #pragma unroll
        for (int n=0;n<8;n++){
            float2 p;
            p.x=oacc[n][0]; p.y=oacc[n][1];
            *(float2*)&sO[orow*72 + n*8 + 2*lr] = p;
            p.x=oacc[n][2]; p.y=oacc[n][3];
            *(float2*)&sO[(orow+8)*72 + n*8 + 2*lr] = p;
        }
    }
    __syncthreads();
    if (khalf == 0){
        int b = bh>>4, h = bh&15;
        float* o0 = out + ((size_t)b*L_ + qb0 + orow)*D_ + h*DH_;
        #pragma unroll
        for (int n=0;n<8;n++){
            float2 p = *(float2*)&sO[orow*72 + n*8 + 2*lr];
            float2 q = *(float2*)&sO[(orow+8)*72 + n*8 + 2*lr];
            float2 r;
            r.x = oacc[n][0]+p.x; r.y = oacc[n][1]+p.y;
            *(float2*)&o0[n*8 + 2*lr] = r;
            r.x = oacc[n][2]+q.x; r.y = oacc[n][3]+q.y;
            *(float2*)&o0[8*(size_t)D_ + n*8 + 2*lr] = r;
        }
    }
}

// ================= launch =================
extern "C" void kernel_launch(void* const* d_in, const int* in_sizes, int n_in,
                              void* d_out, int out_size)
{
    const float* query = (const float*)d_in[0];
    const float* key_  = (const float*)d_in[1];
    const float* value = (const float*)d_in[2];
    const float* w_q   = (const float*)d_in[3];
    const float* w_k   = (const float*)d_in[4];
    const float* w_v   = (const float*)d_in[5];
    float* out = (float*)d_out;

    __nv_bfloat16 *qh,*ql,*kh,*kl,*vh,*vl;
    cudaGetSymbolAddress((void**)&qh, g_qhi);
    cudaGetSymbolAddress((void**)&ql, g_qlo);
    cudaGetSymbolAddress((void**)&kh, g_khi);
    cudaGetSymbolAddress((void**)&kl, g_klo);
    cudaGetSymbolAddress((void**)&vh, g_vhi);
    cudaGetSymbolAddress((void**)&vl, g_vlo);

    dim3 pg(8192/128, D_/128);   // (64, 8)
    proj3_kernel<<<pg, 256>>>(query, w_q, qh, ql);
    proj3_kernel<<<pg, 256>>>(key_,  w_k, kh, kl);
    proj3_kernel<<<pg, 256>>>(value, w_v, vh, vl);

    cudaFuncSetAttribute(attn_mma_kernel,
                         cudaFuncAttributeMaxDynamicSharedMemorySize, ASMEM);

    long long need = (long long)B_*L_*D_ + (long long)BH_*L_*L_;
    int write_attn = ((long long)out_size >= need) ? 1 : 0;
    float* attn = out + (size_t)B_*L_*D_;

    dim3 ag(L_/AQ, BH_);         // (32, 64)
    attn_mma_kernel<<<ag, 256, ASMEM>>>(out, attn, write_attn);
}

// round 12
// speedup vs baseline: 3.5991x; 1.0359x over previous
#include <cuda_runtime.h>
#include <cuda_bf16.h>
#include <math.h>
#include <stdint.h>

#define B_  4
#define L_  2048
#define D_  1024
#define H_  16
#define DH_ 64
#define BH_ (B_*H_)

// bf16 hi/lo planes, [bh][l][dh]
__device__ __nv_bfloat16 g_qhi[(size_t)BH_*L_*DH_];
__device__ __nv_bfloat16 g_qlo[(size_t)BH_*L_*DH_];
__device__ __nv_bfloat16 g_khi[(size_t)BH_*L_*DH_];
__device__ __nv_bfloat16 g_klo[(size_t)BH_*L_*DH_];
__device__ __nv_bfloat16 g_vhi[(size_t)BH_*L_*DH_];
__device__ __nv_bfloat16 g_vlo[(size_t)BH_*L_*DH_];

__device__ __forceinline__ void mma_bf(float (&c)[4], uint32_t a0, uint32_t a1,
                                       uint32_t a2, uint32_t a3,
                                       uint32_t b0, uint32_t b1)
{
    asm volatile(
        "mma.sync.aligned.m16n8k16.row.col.f32.bf16.bf16.f32 "
        "{%0,%1,%2,%3},{%4,%5,%6,%7},{%8,%9},{%0,%1,%2,%3};\n"
        : "+f"(c[0]), "+f"(c[1]), "+f"(c[2]), "+f"(c[3])
        : "r"(a0), "r"(a1), "r"(a2), "r"(a3), "r"(b0), "r"(b1));
}

__device__ __forceinline__ void split_pack(float x, float y, uint32_t& h, uint32_t& l)
{
    __nv_bfloat16 hx = __float2bfloat16_rn(x);
    __nv_bfloat16 hy = __float2bfloat16_rn(y);
    __nv_bfloat16 lx = __float2bfloat16_rn(x - __bfloat162float(hx));
    __nv_bfloat16 ly = __float2bfloat16_rn(y - __bfloat162float(hy));
    __nv_bfloat162 hh; hh.x = hx; hh.y = hy;
    __nv_bfloat162 ll; ll.x = lx; ll.y = ly;
    h = *reinterpret_cast<uint32_t*>(&hh);
    l = *reinterpret_cast<uint32_t*>(&ll);
}

// ================= projection: Y = X @ W^T (bf16x3 MMA) =================
#define PJW 20   // smem row stride in words (40 halves = 32 data + 8 pad)

__global__ __launch_bounds__(256, 2)
void proj3_kernel(const float* __restrict__ X, const float* __restrict__ W,
                  __nv_bfloat16* __restrict__ Yh, __nv_bfloat16* __restrict__ Yl)
{
    __shared__ uint32_t sb[4*128*PJW];
    const int AHI = 0, ALO = 2560, BHI = 5120, BLO = 7680;

    const int tid = threadIdx.x;
    const int w = tid>>5, lane = tid&31, l4 = lane>>2, lr = lane&3;
    const int wM = w>>1, wN = w&1;
    const int m0 = blockIdx.x*128, n0 = blockIdx.y*128;
    const int row = tid>>1, kq = (tid&1)*16;

    const float* xp = X + (size_t)(m0+row)*D_ + kq;
    const float* wp = W + (size_t)(n0+row)*D_ + kq;

    float acc[2][8][4];
    #pragma unroll
    for (int mt=0;mt<2;mt++)
        #pragma unroll
        for (int nt=0;nt<8;nt++)
            #pragma unroll
            for (int i=0;i<4;i++) acc[mt][nt][i] = 0.f;

    float4 ax[4], bx[4];
    #pragma unroll
    for (int i=0;i<4;i++){ ax[i] = *(const float4*)&xp[4*i]; bx[i] = *(const float4*)&wp[4*i]; }

    for (int k0 = 0; k0 < D_; k0 += 32) {
        const int dw = row*PJW + (kq>>1);
        #pragma unroll
        for (int i=0;i<4;i++){
            uint32_t h0,l0,h1,l1;
            split_pack(ax[i].x, ax[i].y, h0, l0);
            split_pack(ax[i].z, ax[i].w, h1, l1);
            sb[AHI+dw+2*i] = h0; sb[AHI+dw+2*i+1] = h1;
            sb[ALO+dw+2*i] = l0; sb[ALO+dw+2*i+1] = l1;
            split_pack(bx[i].x, bx[i].y, h0, l0);
            split_pack(bx[i].z, bx[i].w, h1, l1);
            sb[BHI+dw+2*i] = h0; sb[BHI+dw+2*i+1] = h1;
            sb[BLO+dw+2*i] = l0; sb[BLO+dw+2*i+1] = l1;
        }
        __syncthreads();
        if (k0 + 32 < D_) {
            #pragma unroll
            for (int i=0;i<4;i++){
                ax[i] = *(const float4*)&xp[k0+32+4*i];
                bx[i] = *(const float4*)&wp[k0+32+4*i];
            }
        }
        #pragma unroll
        for (int kt=0;kt<2;kt++){
            uint32_t ah[2][4], al[2][4];
            #pragma unroll
            for (int mt=0;mt<2;mt++){
                int aw = (wM*32 + mt*16 + l4)*PJW + kt*8 + lr;
                ah[mt][0]=sb[AHI+aw];       ah[mt][1]=sb[AHI+aw+8*PJW];
                ah[mt][2]=sb[AHI+aw+4];     ah[mt][3]=sb[AHI+aw+8*PJW+4];
                al[mt][0]=sb[ALO+aw];       al[mt][1]=sb[ALO+aw+8*PJW];
                al[mt][2]=sb[ALO+aw+4];     al[mt][3]=sb[ALO+aw+8*PJW+4];
            }
            #pragma unroll
            for (int nt=0;nt<8;nt++){
                int bw = (wN*64 + nt*8 + l4)*PJW + kt*8 + lr;
                uint32_t bh0=sb[BHI+bw], bh1=sb[BHI+bw+4];
                uint32_t bl0=sb[BLO+bw], bl1=sb[BLO+bw+4];
                #pragma unroll
                for (int mt=0;mt<2;mt++){
                    mma_bf(acc[mt][nt], ah[mt][0],ah[mt][1],ah[mt][2],ah[mt][3], bh0,bh1);
                    mma_bf(acc[mt][nt], al[mt][0],al[mt][1],al[mt][2],al[mt][3], bh0,bh1);
                    mma_bf(acc[mt][nt], ah[mt][0],ah[mt][1],ah[mt][2],ah[mt][3], bl0,bl1);
                }
            }
        }
        __syncthreads();
    }

    // epilogue -> hi/lo planes [bh][l][dh]
    #pragma unroll
    for (int mt=0;mt<2;mt++){
        #pragma unroll
        for (int nt=0;nt<8;nt++){
            int m = m0 + wM*32 + mt*16 + l4;
            int n = n0 + wN*64 + nt*8 + 2*lr;
            int b = m>>11, l = m&2047, h = n>>6, dh = n&63;
            size_t o = (((size_t)(b*H_+h)*L_) + l)*DH_ + dh;
            uint32_t hi, lo;
            split_pack(acc[mt][nt][0], acc[mt][nt][1], hi, lo);
            *(uint32_t*)(Yh+o) = hi; *(uint32_t*)(Yl+o) = lo;
            split_pack(acc[mt][nt][2], acc[mt][nt][3], hi, lo);
            *(uint32_t*)(Yh+o+8*DH_) = hi; *(uint32_t*)(Yl+o+8*DH_) = lo;
        }
    }
}

// ================= attention (bf16x3 MMA, fused single sweep) =================
#define AQ  64
#define ACH 128
#define NCH (L_/ACH)
#define QW  36     // q/k row stride words (72 halves)
#define VW  68     // vt row stride words (136 halves)
// word bases
#define QHW 0
#define QLW 2304
#define KHW 4608
#define KLW 9216
#define VHW 13824
#define VLW 18176
#define FLT_OFF 90112
#define ASMEM 109312
#define SCL 0.125f

__device__ __forceinline__ void compute_S(const uint32_t* sw, int qbase, int kb,
                                          float (&acc)[8][4])
{
    #pragma unroll
    for (int n=0;n<8;n++){ acc[n][0]=0.f; acc[n][1]=0.f; acc[n][2]=0.f; acc[n][3]=0.f; }
    #pragma unroll
    for (int kt=0;kt<4;kt++){
        int aw = qbase + kt*8;
        uint32_t ah0=sw[QHW+aw], ah1=sw[QHW+aw+8*QW], ah2=sw[QHW+aw+4], ah3=sw[QHW+aw+8*QW+4];
        uint32_t al0=sw[QLW+aw], al1=sw[QLW+aw+8*QW], al2=sw[QLW+aw+4], al3=sw[QLW+aw+8*QW+4];
        #pragma unroll
        for (int n=0;n<8;n++){
            int bw = kb + n*8*QW + kt*8;
            uint32_t bh0=sw[KHW+bw], bh1=sw[KHW+bw+4];
            uint32_t bl0=sw[KLW+bw], bl1=sw[KLW+bw+4];
            mma_bf(acc[n], ah0,ah1,ah2,ah3, bh0,bh1);
            mma_bf(acc[n], al0,al1,al2,al3, bh0,bh1);
            mma_bf(acc[n], ah0,ah1,ah2,ah3, bl0,bl1);
        }
    }
}

__global__ __launch_bounds__(256, 2)
void attn_mma_kernel(float* __restrict__ out, float* __restrict__ attn, int write_attn)
{
    extern __shared__ char smem_raw[];
    uint32_t* sw = (uint32_t*)smem_raw;
    __nv_bfloat16* sh = (__nv_bfloat16*)smem_raw;
    float* sPart = (float*)(smem_raw + FLT_OFF);
    float* sInv  = sPart + 128;
    float* sO    = sInv + 64;

    const int tid = threadIdx.x;
    const int w = tid>>5, lane = tid&31, l4 = lane>>2, lr = lane&3;
    const int mstrip = w>>1, khalf = w&1;
    const int bh = blockIdx.y;
    const int qb0 = blockIdx.x*AQ;

    // stage Q (contiguous 512 uint4 per plane)
    {
        const uint4* s1 = (const uint4*)(g_qhi + ((size_t)bh*L_ + qb0)*DH_);
        const uint4* s2 = (const uint4*)(g_qlo + ((size_t)bh*L_ + qb0)*DH_);
        #pragma unroll
        for (int i=0;i<2;i++){
            int j = tid + i*256;
            int dw = (j>>3)*QW + (j&7)*4;
            *(uint4*)&sw[QHW+dw] = s1[j];
            *(uint4*)&sw[QLW+dw] = s2[j];
        }
    }
    __syncthreads();

    const int qbase = (mstrip*16 + l4)*QW + lr;
    const int kb    = (khalf*64 + l4)*QW + lr;

    const __nv_bfloat16* Kh = g_khi + (size_t)bh*L_*DH_;
    const __nv_bfloat16* Kl = g_klo + (size_t)bh*L_*DH_;
    const __nv_bfloat16* Vh = g_vhi + (size_t)bh*L_*DH_;
    const __nv_bfloat16* Vl = g_vlo + (size_t)bh*L_*DH_;

    float rs0 = 0.f, rs1 = 0.f;
    float oacc[8][4];
    #pragma unroll
    for (int n=0;n<8;n++){ oacc[n][0]=0.f; oacc[n][1]=0.f; oacc[n][2]=0.f; oacc[n][3]=0.f; }

    float* attnRow = attn + ((size_t)bh*L_ + qb0 + mstrip*16 + l4)*L_;
    const int colb = khalf*64 + 2*lr;

    // ---- fused single sweep: S once; raw e -> attn; rs += e; O += e*V ----
    for (int kc=0;kc<NCH;kc++){
        const uint4* skh = (const uint4*)(Kh + (size_t)kc*ACH*DH_);
        const uint4* skl = (const uint4*)(Kl + (size_t)kc*ACH*DH_);
        const uint4* svh = (const uint4*)(Vh + (size_t)kc*ACH*DH_);
        const uint4* svl = (const uint4*)(Vl + (size_t)kc*ACH*DH_);
        uint4 t0=skh[tid], t1=skh[tid+256], t2=skh[tid+512], t3=skh[tid+768];
        uint4 u0=skl[tid], u1=skl[tid+256], u2=skl[tid+512], u3=skl[tid+768];
        __syncthreads();
        {
            int j0=tid, j1=tid+256, j2=tid+512, j3=tid+768;
            *(uint4*)&sw[KHW+(j0>>3)*QW+(j0&7)*4] = t0;
            *(uint4*)&sw[KHW+(j1>>3)*QW+(j1&7)*4] = t1;
            *(uint4*)&sw[KHW+(j2>>3)*QW+(j2&7)*4] = t2;
            *(uint4*)&sw[KHW+(j3>>3)*QW+(j3&7)*4] = t3;
            *(uint4*)&sw[KLW+(j0>>3)*QW+(j0&7)*4] = u0;
            *(uint4*)&sw[KLW+(j1>>3)*QW+(j1&7)*4] = u1;
            *(uint4*)&sw[KLW+(j2>>3)*QW+(j2&7)*4] = u2;
            *(uint4*)&sw[KLW+(j3>>3)*QW+(j3&7)*4] = u3;
        }
        // Vt staging (transpose in smem), XOR-swizzled half-column:
        // physical half col = l ^ ((dh>>3)<<1); here dh>>3 == (j&7) for all 8 q's.
        #pragma unroll
        for (int i=0;i<4;i++){
            int j = tid + i*256;
            uint4 v = svh[j];
            uint4 x = svl[j];
            int r = j>>3, sg = (j&7)*8;
            int rs = r ^ ((j&7)<<1);
            const __nv_bfloat16* pv = (const __nv_bfloat16*)&v;
            const __nv_bfloat16* px = (const __nv_bfloat16*)&x;
            #pragma unroll
            for (int q=0;q<8;q++){
                sh[2*VHW + (sg+q)*136 + rs] = pv[q];
                sh[2*VLW + (sg+q)*136 + rs] = px[q];
            }
        }
        __syncthreads();

        float acc[8][4];
        compute_S(sw, qbase, kb, acc);

        const int cb = kc*ACH + colb;
        #pragma unroll
        for (int j=0;j<4;j++){
            float e00=__expf(acc[2*j][0]*SCL),   e01=__expf(acc[2*j][1]*SCL);
            float e02=__expf(acc[2*j][2]*SCL),   e03=__expf(acc[2*j][3]*SCL);
            float f00=__expf(acc[2*j+1][0]*SCL), f01=__expf(acc[2*j+1][1]*SCL);
            float f02=__expf(acc[2*j+1][2]*SCL), f03=__expf(acc[2*j+1][3]*SCL);
            rs0 += e00+e01+f00+f01;
            rs1 += e02+e03+f02+f03;
            if (write_attn){
                float2 p;
                p.x=e00; p.y=e01; *(float2*)&attnRow[cb + j*16]          = p;
                p.x=e02; p.y=e03; *(float2*)&attnRow[8*L_ + cb + j*16]   = p;
                p.x=f00; p.y=f01; *(float2*)&attnRow[cb + j*16 + 8]      = p;
                p.x=f02; p.y=f03; *(float2*)&attnRow[8*L_ + cb + j*16+8] = p;
            }
            uint32_t a0h,a0l,a1h,a1l,a2h,a2l,a3h,a3l;
            split_pack(e00,e01,a0h,a0l);
            split_pack(e02,e03,a1h,a1l);
            split_pack(f00,f01,a2h,a2l);
            split_pack(f02,f03,a3h,a3l);
            const int cw = lr + khalf*32 + j*8;   // pre-swizzle word col
            #pragma unroll
            for (int n=0;n<8;n++){
                int rowb = (n*8 + l4)*VW;
                int b0 = rowb + (cw ^ n);
                int b1 = rowb + ((cw + 4) ^ n);
                uint32_t vh0=sw[VHW+b0], vh1=sw[VHW+b1];
                uint32_t vl0=sw[VLW+b0], vl1=sw[VLW+b1];
                mma_bf(oacc[n], a0h,a1h,a2h,a3h, vh0,vh1);
                mma_bf(oacc[n], a0l,a1l,a2l,a3l, vh0,vh1);
                mma_bf(oacc[n], a0h,a1h,a2h,a3h, vl0,vl1);
            }
        }
    }

    // ---- row-sum reduction -> inv ----
    rs0 += __shfl_xor_sync(0xffffffffu, rs0, 1);
    rs0 += __shfl_xor_sync(0xffffffffu, rs0, 2);
    rs1 += __shfl_xor_sync(0xffffffffu, rs1, 1);
    rs1 += __shfl_xor_sync(0xffffffffu, rs1, 2);
    if (lr == 0){
        sPart[khalf*64 + mstrip*16 + l4]     = rs0;
        sPart[khalf*64 + mstrip*16 + l4 + 8] = rs1;
    }
    __syncthreads();
    if (tid < 64) sInv[tid] = 1.f / (sPart[tid] + sPart[64+tid]);
    __syncthreads();

    const float inv0 = sInv[mstrip*16 + l4];
    const float inv1 = sInv[mstrip*16 + l4 + 8];
    #pragma unroll
    for (int n=0;n<8;n++){
        oacc[n][0]*=inv0; oacc[n][1]*=inv0;
        oacc[n][2]*=inv1; oacc[n][3]*=inv1;
    }

    // O cross-warp (khalf) reduction + writeback
    const int orow = mstrip*16 + l4;
    if (khalf == 1){
        #pragma unroll
        for (int n=0;n<8;n++){
            float2 p;
            p.x=oacc[n][0]; p.y=oacc[n][1];
            *(float2*)&sO[orow*72 + n*8 + 2*lr] = p;
            p.x=oacc[n][2]; p.y=oacc[n][3];
            *(float2*)&sO[(orow+8)*72 + n*8 + 2*lr] = p;
        }
    }
    __syncthreads();
    if (khalf == 0){
        int b = bh>>4, h = bh&15;
        float* o0 = out + ((size_t)b*L_ + qb0 + orow)*D_ + h*DH_;
        #pragma unroll
        for (int n=0;n<8;n++){
            float2 p = *(float2*)&sO[orow*72 + n*8 + 2*lr];
            float2 q = *(float2*)&sO[(orow+8)*72 + n*8 + 2*lr];
            float2 r;
            r.x = oacc[n][0]+p.x; r.y = oacc[n][1]+p.y;
            *(float2*)&o0[n*8 + 2*lr] = r;
            r.x = oacc[n][2]+q.x; r.y = oacc[n][3]+q.y;
            *(float2*)&o0[8*(size_t)D_ + n*8 + 2*lr] = r;
        }
    }

    // ---- in-place attn normalization (this CTA's 64 rows) ----
    if (write_attn){
        __syncthreads();   // all raw-e writes by this CTA done & visible
        float4* base = (float4*)(attn + ((size_t)bh*L_ + qb0)*L_);
        #pragma unroll 4
        for (int i=tid; i<(AQ*L_)/4; i+=256){
            int r = i >> 9;              // i*4 / 2048
            float s = sInv[r];
            float4 v = base[i];
            v.x*=s; v.y*=s; v.z*=s; v.w*=s;
            base[i] = v;
        }
    }
}

// ================= launch =================
extern "C" void kernel_launch(void* const* d_in, const int* in_sizes, int n_in,
                              void* d_out, int out_size)
{
    const float* query = (const float*)d_in[0];
    const float* key_  = (const float*)d_in[1];
    const float* value = (const float*)d_in[2];
    const float* w_q   = (const float*)d_in[3];
    const float* w_k   = (const float*)d_in[4];
    const float* w_v   = (const float*)d_in[5];
    float* out = (float*)d_out;

    __nv_bfloat16 *qh,*ql,*kh,*kl,*vh,*vl;
    cudaGetSymbolAddress((void**)&qh, g_qhi);
    cudaGetSymbolAddress((void**)&ql, g_qlo);
    cudaGetSymbolAddress((void**)&kh, g_khi);
    cudaGetSymbolAddress((void**)&kl, g_klo);
    cudaGetSymbolAddress((void**)&vh, g_vhi);
    cudaGetSymbolAddress((void**)&vl, g_vlo);

    dim3 pg(8192/128, D_/128);   // (64, 8)
    proj3_kernel<<<pg, 256>>>(query, w_q, qh, ql);
    proj3_kernel<<<pg, 256>>>(key_,  w_k, kh, kl);
    proj3_kernel<<<pg, 256>>>(value, w_v, vh, vl);

    cudaFuncSetAttribute(attn_mma_kernel,
                         cudaFuncAttributeMaxDynamicSharedMemorySize, ASMEM);

    long long need = (long long)B_*L_*D_ + (long long)BH_*L_*L_;
    int write_attn = ((long long)out_size >= need) ? 1 : 0;
    float* attn = out + (size_t)B_*L_*D_;

    dim3 ag(L_/AQ, BH_);         // (32, 64)
    attn_mma_kernel<<<ag, 256, ASMEM>>>(out, attn, write_attn);
}